// round 15
// baseline (speedup 1.0000x reference)
#include <cuda_runtime.h>
#include <cuda_fp16.h>
#include <cstdint>

#define NEXP   8
#define DIM_S  64
#define HID    256
#define BM     64
#define NTHR   128

// Pre-shuffled fp16 B-fragment streams (built by convw each launch).
// Layout: [c][wn][ks][quarter q4=rg*2+nthalf][lane][j(=nt within half)] u32
//   u32 = {W[k][n], W[k+1][n]},  k = ks*16 + (lane&3)*2 + 8*rg,
//   n = wn*64 + nt*8 + (lane>>2),  nt = (q4&1)*4 + j
__device__ uint32_t g_w1s[NEXP * 4 * 4 * 512];    //  65536 u32
__device__ uint32_t g_w2s[NEXP * 4 * 16 * 512];   // 262144 u32

// ---- SMEM (bytes) ----
// A1: fp16 [64 r][64 k], 128 B/row, chunk(16B) swizzle: chunk ^= (row&7)
// H1: fp16 [64 r][256 k], 512 B/row, same swizzle (low 3 chunk bits)
#define OFF_A1    0
#define OFF_H1    8192
#define OFF_B1    40960          // u32[128]: b1 as half2 col-pairs
#define OFF_B2    41472          // u32[128]: b2 as half2 col-pairs
#define OFF_W3    41984          // u32[128]: w3 as half2 col-pairs
#define OFF_PART  42496          // [64 rows][4 wn] f32
#define SMEM_BYTES 43520

__device__ __forceinline__ uint32_t packh2(float lo, float hi) {
    __half2 h = __floats2half2_rn(lo, hi);
    return *reinterpret_cast<uint32_t*>(&h);
}
__device__ __forceinline__ __half2 u2h(uint32_t x) {
    return *reinterpret_cast<__half2*>(&x);
}
__device__ __forceinline__ uint32_t smem_u32(const void* p) {
    uint32_t a;
    asm("{ .reg .u64 t; cvta.to.shared.u64 t, %1; cvt.u32.u64 %0, t; }" : "=r"(a) : "l"(p));
    return a;
}
// f16-accumulate MMA: C/D are 2 x f16x2 regs.
__device__ __forceinline__ void mma_h(uint32_t c[2], const uint32_t* a,
                                      uint32_t b0, uint32_t b1) {
    asm volatile(
        "mma.sync.aligned.m16n8k16.row.col.f16.f16.f16.f16 "
        "{%0,%1}, {%2,%3,%4,%5}, {%6,%7}, {%0,%1};"
        : "+r"(c[0]), "+r"(c[1])
        : "r"(a[0]), "r"(a[1]), "r"(a[2]), "r"(a[3]), "r"(b0), "r"(b1));
}
__device__ __forceinline__ void ldmx4(uint32_t* a, uint32_t addr) {
    asm volatile("ldmatrix.sync.aligned.m8n8.x4.shared.b16 {%0,%1,%2,%3}, [%4];"
        : "=r"(a[0]), "=r"(a[1]), "=r"(a[2]), "=r"(a[3]) : "r"(addr));
}
__device__ __forceinline__ uint32_t hadd2u(uint32_t x, uint32_t y) {
    __half2 r = __hadd2(u2h(x), u2h(y));
    return *reinterpret_cast<uint32_t*>(&r);
}
__device__ __forceinline__ uint32_t hmax2z(uint32_t x) {
    __half2 z = __float2half2_rn(0.f);
    __half2 r = __hmax2(u2h(x), z);
    return *reinterpret_cast<uint32_t*>(&r);
}

// Load one ks-step of B fragments from a pre-offset uint4 pointer.
__device__ __forceinline__ void loadBfrag(const uint4* __restrict__ p,
                                          uint32_t* b) {
    uint4 v0 = __ldg(p);        // rg0, nt0-3
    uint4 v1 = __ldg(p + 32);   // rg0, nt4-7
    uint4 v2 = __ldg(p + 64);   // rg1, nt0-3
    uint4 v3 = __ldg(p + 96);   // rg1, nt4-7
    b[0]  = v0.x; b[2]  = v0.y; b[4]  = v0.z; b[6]  = v0.w;
    b[8]  = v1.x; b[10] = v1.y; b[12] = v1.z; b[14] = v1.w;
    b[1]  = v2.x; b[3]  = v2.y; b[5]  = v2.z; b[7]  = v2.w;
    b[9]  = v3.x; b[11] = v3.y; b[13] = v3.z; b[15] = v3.w;
}

// ---- prologue: build B-fragment streams from fp32 row-major weights ----
__global__ void __launch_bounds__(256)
convw(const float* __restrict__ W1, const float* __restrict__ W2)
{
    int i = blockIdx.x * 256 + threadIdx.x;
    if (i < NEXP * 4 * 4 * 512) {            // W1 stream
        int j = i & 3, lane = (i >> 2) & 31, q4 = (i >> 7) & 3;
        int ks = (i >> 9) & 3, w = (i >> 11) & 3, c = i >> 13;
        int rg = q4 >> 1, nt = (q4 & 1) * 4 + j;
        int n = w * 64 + nt * 8 + (lane >> 2);
        int k = ks * 16 + (lane & 3) * 2 + rg * 8;
        const float* p = W1 + ((size_t)c * DIM_S + k) * HID + n;
        g_w1s[i] = packh2(p[0], p[HID]);
    } else {
        i -= NEXP * 4 * 4 * 512;
        if (i < NEXP * 4 * 16 * 512) {       // W2 stream
            int j = i & 3, lane = (i >> 2) & 31, q4 = (i >> 7) & 3;
            int ks = (i >> 9) & 15, w = (i >> 13) & 3, c = i >> 15;
            int rg = q4 >> 1, nt = (q4 & 1) * 4 + j;
            int n = w * 64 + nt * 8 + (lane >> 2);
            int k = ks * 16 + (lane & 3) * 2 + rg * 8;
            const float* p = W2 + ((size_t)c * HID + k) * HID + n;
            g_w2s[i] = packh2(p[0], p[HID]);
        }
    }
}

// GEMM (f16 acc): ks < SPLIT accumulates into accA, ks >= SPLIT into accB.
// A rows 0..63, K = TOT16*16, smem swizzled row-major fp16, ROWB bytes/row.
// B: single-buffer, loaded per-ks (streams are L1-resident across CTAs).
template<int TOT16, int SPLIT, int ROWB>
__device__ __forceinline__ void gemm(const uint4* __restrict__ pb,
                                     uint32_t afb,
                                     uint32_t accA[4][8][2],
                                     uint32_t accB[4][8][2],
                                     int lane)
{
    const int arow = ((lane >> 3) & 1) * 8 + (lane & 7);
    const int jj   = lane >> 4;
    const uint32_t abase = afb + arow * ROWB;
    const int      amask = arow & 7;

    uint32_t areg[2][4];
    uint32_t breg[16];

    auto loadA = [&](int ks, int mt, uint32_t* a) {
        int chunk = (2 * ks + jj) ^ amask;
        ldmx4(a, abase + mt * 16 * ROWB + chunk * 16);
    };

    loadA(0, 0, areg[0]);

    #pragma unroll
    for (int ks = 0; ks < TOT16; ks++) {
        loadBfrag(pb, breg);
        pb += 128;
        #pragma unroll
        for (int mt = 0; mt < 4; mt++) {
            if (!(mt == 3 && ks + 1 == TOT16))
                loadA(mt == 3 ? ks + 1 : ks, (mt + 1) & 3, areg[(mt + 1) & 1]);
            const uint32_t* a = areg[mt & 1];
            #pragma unroll
            for (int nt = 0; nt < 8; nt++)
                mma_h(ks < SPLIT ? accA[mt][nt] : accB[mt][nt],
                      a, breg[nt * 2], breg[nt * 2 + 1]);
        }
    }
}

__global__ void __launch_bounds__(NTHR, 3)
moe_disc_mma(const float* __restrict__ st,
             const float* __restrict__ b1, const float* __restrict__ b2,
             const float* __restrict__ W3, const float* __restrict__ b3,
             float* __restrict__ out)
{
    extern __shared__ char smem[];
    float* smf = reinterpret_cast<float*>(smem);
    uint32_t* smu = reinterpret_cast<uint32_t*>(smem);
    const uint32_t sb = smem_u32(smem);
    const int tid  = threadIdx.x;
    const int wn   = tid >> 5;        // 0..3 : 64-col block
    const int lane = tid & 31;
    const int c    = blockIdx.y;
    const int m0   = blockIdx.x * BM;

    const uint4* pb1 = reinterpret_cast<const uint4*>(
        g_w1s + ((size_t)(c * 4 + wn)) * 2048) + lane;
    const uint4* pb2 = reinterpret_cast<const uint4*>(
        g_w2s + ((size_t)(c * 4 + wn)) * 8192) + lane;

    // ---- stage b1/b2/w3 as half2 col-pairs, and A1 ----
    {
        float2 v1 = *reinterpret_cast<const float2*>(b1 + c * HID + 2 * tid);
        float2 v2 = *reinterpret_cast<const float2*>(b2 + c * HID + 2 * tid);
        float2 v3 = *reinterpret_cast<const float2*>(W3 + c * HID + 2 * tid);
        smu[(OFF_B1 >> 2) + tid] = packh2(v1.x, v1.y);
        smu[(OFF_B2 >> 2) + tid] = packh2(v2.x, v2.y);
        smu[(OFF_W3 >> 2) + tid] = packh2(v3.x, v3.y);
    }

    #pragma unroll
    for (int i = 0; i < 8; i++) {
        int idx = tid + i * NTHR;       // 0..1023 float4
        int row = idx >> 4, f4 = idx & 15;
        float4 v = *reinterpret_cast<const float4*>(
            st + (size_t)(m0 + row) * DIM_S + f4 * 4);
        uint32_t byte = OFF_A1 + row * 128
                      + (uint32_t)(((f4 >> 1) ^ (row & 7)) * 16 + 8 * (f4 & 1));
        *reinterpret_cast<uint2*>(smem + byte) =
            make_uint2(packh2(v.x, v.y), packh2(v.z, v.w));
    }
    __syncthreads();

    uint32_t accA[4][8][2], accB[4][8][2];
    #pragma unroll
    for (int a = 0; a < 4; a++)
        #pragma unroll
        for (int b = 0; b < 8; b++) {
            accA[a][b][0] = 0u; accA[a][b][1] = 0u;
        }

    // ---- layer 1 GEMM (K = 64, single f16 chain into accA) ----
    gemm<4, 8, 128>(pb1, sb + OFF_A1, accA, accB, lane);

    // ---- epilogue 1: H1 = hmax2(accA + b1h2, 0), direct half2 STS ----
    // phys col pair of accA[mt][nt][r2] = wn*64 + nt*8 + 2*(lane&3)
    {
        uint32_t b1p[8];
        #pragma unroll
        for (int nt = 0; nt < 8; nt++)
            b1p[nt] = smu[(OFF_B1 >> 2) + wn * 32 + nt * 4 + (lane & 3)];
        const int c0 = (lane >> 2) & 7;
        const uint32_t eb = OFF_H1 + (lane >> 2) * 512 + wn * 128
                          + 4 * (lane & 3);
        #pragma unroll
        for (int mt = 0; mt < 4; mt++) {
            const uint32_t ebm = eb + mt * 8192;
            #pragma unroll
            for (int nt = 0; nt < 8; nt++) {
                uint32_t p0 = hmax2z(hadd2u(accA[mt][nt][0], b1p[nt]));
                uint32_t p1 = hmax2z(hadd2u(accA[mt][nt][1], b1p[nt]));
                uint32_t by0 = ebm + (uint32_t)((nt ^ c0) * 16);
                *reinterpret_cast<uint32_t*>(smem + by0) = p0;
                *reinterpret_cast<uint32_t*>(smem + by0 + 4096) = p1;
            }
        }
    }
    #pragma unroll
    for (int a = 0; a < 4; a++)
        #pragma unroll
        for (int b = 0; b < 8; b++) {
            accA[a][b][0] = 0u; accA[a][b][1] = 0u;
            accB[a][b][0] = 0u; accB[a][b][1] = 0u;
        }

    __syncthreads();   // H1 visible

    // ---- layer 2 GEMM (K = 256): two 8-step f16 chains (accA, accB) ----
    gemm<16, 8, 512>(pb2, sb + OFF_H1, accA, accB, lane);

    // ---- epilogue 2: v = hmax2(accA+accB+b2) in half2; dot w3 in f32 ----
    {
        uint32_t b2p[8];
        float2 w3f[8];
        #pragma unroll
        for (int nt = 0; nt < 8; nt++) {
            int idx = wn * 32 + nt * 4 + (lane & 3);
            b2p[nt] = smu[(OFF_B2 >> 2) + idx];
            w3f[nt] = __half22float2(u2h(smu[(OFF_W3 >> 2) + idx]));
        }
        float p[4][2];
        #pragma unroll
        for (int mt = 0; mt < 4; mt++) { p[mt][0] = 0.f; p[mt][1] = 0.f; }
        #pragma unroll
        for (int mt = 0; mt < 4; mt++)
            #pragma unroll
            for (int nt = 0; nt < 8; nt++)
                #pragma unroll
                for (int r2 = 0; r2 < 2; r2++) {
                    uint32_t s = hadd2u(accA[mt][nt][r2], accB[mt][nt][r2]);
                    uint32_t v = hmax2z(hadd2u(s, b2p[nt]));
                    float2 fv = __half22float2(u2h(v));
                    p[mt][r2] += fv.x * w3f[nt].x + fv.y * w3f[nt].y;
                }
        #pragma unroll
        for (int off = 1; off <= 2; off <<= 1)
            #pragma unroll
            for (int mt = 0; mt < 4; mt++) {
                p[mt][0] += __shfl_xor_sync(0xFFFFFFFFu, p[mt][0], off);
                p[mt][1] += __shfl_xor_sync(0xFFFFFFFFu, p[mt][1], off);
            }
        if ((lane & 3) == 0) {
            #pragma unroll
            for (int mt = 0; mt < 4; mt++)
                #pragma unroll
                for (int h = 0; h < 2; h++) {
                    int row = mt * 16 + (lane >> 2) + 8 * h;
                    smf[(OFF_PART >> 2) + row * 4 + wn] = p[mt][h];
                }
        }
    }
    __syncthreads();
    if (tid < BM) {
        const float* q = smf + (OFF_PART >> 2) + tid * 4;
        out[(size_t)(m0 + tid) * NEXP + c] = q[0] + q[1] + q[2] + q[3] + b3[c];
    }
}

extern "C" void kernel_launch(void* const* d_in, const int* in_sizes, int n_in,
                              void* d_out, int out_size)
{
    const float* st = (const float*)d_in[0];
    const float* W1 = (const float*)d_in[1];
    const float* b1 = (const float*)d_in[2];
    const float* W2 = (const float*)d_in[3];
    const float* b2 = (const float*)d_in[4];
    const float* W3 = (const float*)d_in[5];
    const float* b3 = (const float*)d_in[6];
    float* out = (float*)d_out;

    const int total = NEXP * 4 * 4 * 512 + NEXP * 4 * 16 * 512;  // 327680
    convw<<<(total + 255) / 256, 256>>>(W1, W2);

    cudaFuncSetAttribute(moe_disc_mma,
                         cudaFuncAttributeMaxDynamicSharedMemorySize, SMEM_BYTES);
    dim3 grid(65536 / BM, NEXP);
    moe_disc_mma<<<grid, NTHR, SMEM_BYTES>>>(st, b1, b2, W3, b3, out);
}

// round 16
// speedup vs baseline: 1.0279x; 1.0279x over previous
#include <cuda_runtime.h>
#include <cuda_fp16.h>
#include <cstdint>

#define NEXP   8
#define DIM_S  64
#define HID    256
#define BM     64
#define NTHR   128
#define NSM    148
#define STAG   2000ll        // cycles per occupancy-slot stagger

// Pre-shuffled fp16 B-fragment streams (built by convw each launch).
// Layout: [c][wn][ks][quarter q4=rg*2+nthalf][lane][j(=nt within half)] u32
//   u32 = {W[k][n], W[k+1][n]},  k = ks*16 + (lane&3)*2 + 8*rg,
//   n = wn*64 + nt*8 + (lane>>2),  nt = (q4&1)*4 + j
__device__ uint32_t g_w1s[NEXP * 4 * 4 * 512];    //  65536 u32
__device__ uint32_t g_w2s[NEXP * 4 * 16 * 512];   // 262144 u32

// ---- SMEM (bytes) ----
// A1: fp16 [64 r][64 k], 128 B/row, chunk(16B) swizzle: chunk ^= (row&7)
// H1: fp16 [64 r][256 k], 512 B/row, same swizzle (low 3 chunk bits)
#define OFF_A1    0
#define OFF_H1    8192
#define OFF_B1    40960          // u32[128]: b1 as half2 col-pairs
#define OFF_B2    41472          // u32[128]: b2 as half2 col-pairs
#define OFF_W3    41984          // u32[128]: w3 as half2 col-pairs
#define OFF_PART  42496          // [64 rows][4 wn] f32
#define SMEM_BYTES 43520

__device__ __forceinline__ uint32_t packh2(float lo, float hi) {
    __half2 h = __floats2half2_rn(lo, hi);
    return *reinterpret_cast<uint32_t*>(&h);
}
__device__ __forceinline__ __half2 u2h(uint32_t x) {
    return *reinterpret_cast<__half2*>(&x);
}
__device__ __forceinline__ uint32_t smem_u32(const void* p) {
    uint32_t a;
    asm("{ .reg .u64 t; cvta.to.shared.u64 t, %1; cvt.u32.u64 %0, t; }" : "=r"(a) : "l"(p));
    return a;
}
// f16-accumulate MMA: C/D are 2 x f16x2 regs.
__device__ __forceinline__ void mma_h(uint32_t c[2], const uint32_t* a,
                                      uint32_t b0, uint32_t b1) {
    asm volatile(
        "mma.sync.aligned.m16n8k16.row.col.f16.f16.f16.f16 "
        "{%0,%1}, {%2,%3,%4,%5}, {%6,%7}, {%0,%1};"
        : "+r"(c[0]), "+r"(c[1])
        : "r"(a[0]), "r"(a[1]), "r"(a[2]), "r"(a[3]), "r"(b0), "r"(b1));
}
__device__ __forceinline__ void ldmx4(uint32_t* a, uint32_t addr) {
    asm volatile("ldmatrix.sync.aligned.m8n8.x4.shared.b16 {%0,%1,%2,%3}, [%4];"
        : "=r"(a[0]), "=r"(a[1]), "=r"(a[2]), "=r"(a[3]) : "r"(addr));
}
__device__ __forceinline__ uint32_t hadd2u(uint32_t x, uint32_t y) {
    __half2 r = __hadd2(u2h(x), u2h(y));
    return *reinterpret_cast<uint32_t*>(&r);
}
__device__ __forceinline__ uint32_t hmax2z(uint32_t x) {
    __half2 z = __float2half2_rn(0.f);
    __half2 r = __hmax2(u2h(x), z);
    return *reinterpret_cast<uint32_t*>(&r);
}

// Load one ks-step of B fragments from a pre-offset uint4 pointer.
__device__ __forceinline__ void loadBfrag(const uint4* __restrict__ p,
                                          uint32_t* b) {
    uint4 v0 = __ldg(p);        // rg0, nt0-3
    uint4 v1 = __ldg(p + 32);   // rg0, nt4-7
    uint4 v2 = __ldg(p + 64);   // rg1, nt0-3
    uint4 v3 = __ldg(p + 96);   // rg1, nt4-7
    b[0]  = v0.x; b[2]  = v0.y; b[4]  = v0.z; b[6]  = v0.w;
    b[8]  = v1.x; b[10] = v1.y; b[12] = v1.z; b[14] = v1.w;
    b[1]  = v2.x; b[3]  = v2.y; b[5]  = v2.z; b[7]  = v2.w;
    b[9]  = v3.x; b[11] = v3.y; b[13] = v3.z; b[15] = v3.w;
}

// ---- prologue: build B-fragment streams from fp32 row-major weights ----
__global__ void __launch_bounds__(256)
convw(const float* __restrict__ W1, const float* __restrict__ W2)
{
    int i = blockIdx.x * 256 + threadIdx.x;
    if (i < NEXP * 4 * 4 * 512) {            // W1 stream
        int j = i & 3, lane = (i >> 2) & 31, q4 = (i >> 7) & 3;
        int ks = (i >> 9) & 3, w = (i >> 11) & 3, c = i >> 13;
        int rg = q4 >> 1, nt = (q4 & 1) * 4 + j;
        int n = w * 64 + nt * 8 + (lane >> 2);
        int k = ks * 16 + (lane & 3) * 2 + rg * 8;
        const float* p = W1 + ((size_t)c * DIM_S + k) * HID + n;
        g_w1s[i] = packh2(p[0], p[HID]);
    } else {
        i -= NEXP * 4 * 4 * 512;
        if (i < NEXP * 4 * 16 * 512) {       // W2 stream
            int j = i & 3, lane = (i >> 2) & 31, q4 = (i >> 7) & 3;
            int ks = (i >> 9) & 15, w = (i >> 13) & 3, c = i >> 15;
            int rg = q4 >> 1, nt = (q4 & 1) * 4 + j;
            int n = w * 64 + nt * 8 + (lane >> 2);
            int k = ks * 16 + (lane & 3) * 2 + rg * 8;
            const float* p = W2 + ((size_t)c * HID + k) * HID + n;
            g_w2s[i] = packh2(p[0], p[HID]);
        }
    }
}

// GEMM (f16 acc): ks < SPLIT accumulates into accA, ks >= SPLIT into accB.
// A rows 0..63, K = TOT16*16, smem swizzled row-major fp16, ROWB bytes/row.
// B: single-buffer, loaded per-ks (streams are L1-resident across CTAs).
template<int TOT16, int SPLIT, int ROWB>
__device__ __forceinline__ void gemm(const uint4* __restrict__ pb,
                                     uint32_t afb,
                                     uint32_t accA[4][8][2],
                                     uint32_t accB[4][8][2],
                                     int lane)
{
    const int arow = ((lane >> 3) & 1) * 8 + (lane & 7);
    const int jj   = lane >> 4;
    const uint32_t abase = afb + arow * ROWB;
    const int      amask = arow & 7;

    uint32_t areg[2][4];
    uint32_t breg[16];

    auto loadA = [&](int ks, int mt, uint32_t* a) {
        int chunk = (2 * ks + jj) ^ amask;
        ldmx4(a, abase + mt * 16 * ROWB + chunk * 16);
    };

    loadA(0, 0, areg[0]);

    #pragma unroll
    for (int ks = 0; ks < TOT16; ks++) {
        loadBfrag(pb, breg);
        pb += 128;
        #pragma unroll
        for (int mt = 0; mt < 4; mt++) {
            if (!(mt == 3 && ks + 1 == TOT16))
                loadA(mt == 3 ? ks + 1 : ks, (mt + 1) & 3, areg[(mt + 1) & 1]);
            const uint32_t* a = areg[mt & 1];
            #pragma unroll
            for (int nt = 0; nt < 8; nt++)
                mma_h(ks < SPLIT ? accA[mt][nt] : accB[mt][nt],
                      a, breg[nt * 2], breg[nt * 2 + 1]);
        }
    }
}

__global__ void __launch_bounds__(NTHR, 3)
moe_disc_mma(const float* __restrict__ st,
             const float* __restrict__ b1, const float* __restrict__ b2,
             const float* __restrict__ W3, const float* __restrict__ b3,
             float* __restrict__ out)
{
    extern __shared__ char smem[];
    float* smf = reinterpret_cast<float*>(smem);
    uint32_t* smu = reinterpret_cast<uint32_t*>(smem);
    const uint32_t sb = smem_u32(smem);
    const int tid  = threadIdx.x;
    const int wn   = tid >> 5;        // 0..3 : 64-col block
    const int lane = tid & 31;
    const int c    = blockIdx.y;
    const int m0   = blockIdx.x * BM;

    // ---- de-phase co-resident CTAs: occupancy-slot stagger ----
    {
        int linbid = blockIdx.y * gridDim.x + blockIdx.x;
        long long d = (long long)((linbid / NSM) % 3) * STAG;
        if (d > 0) {
            long long t0 = clock64();
            while (clock64() - t0 < d) { }
        }
    }

    const uint4* pb1 = reinterpret_cast<const uint4*>(
        g_w1s + ((size_t)(c * 4 + wn)) * 2048) + lane;
    const uint4* pb2 = reinterpret_cast<const uint4*>(
        g_w2s + ((size_t)(c * 4 + wn)) * 8192) + lane;

    // ---- stage b1/b2/w3 as half2 col-pairs, and A1 ----
    {
        float2 v1 = *reinterpret_cast<const float2*>(b1 + c * HID + 2 * tid);
        float2 v2 = *reinterpret_cast<const float2*>(b2 + c * HID + 2 * tid);
        float2 v3 = *reinterpret_cast<const float2*>(W3 + c * HID + 2 * tid);
        smu[(OFF_B1 >> 2) + tid] = packh2(v1.x, v1.y);
        smu[(OFF_B2 >> 2) + tid] = packh2(v2.x, v2.y);
        smu[(OFF_W3 >> 2) + tid] = packh2(v3.x, v3.y);
    }

    #pragma unroll
    for (int i = 0; i < 8; i++) {
        int idx = tid + i * NTHR;       // 0..1023 float4
        int row = idx >> 4, f4 = idx & 15;
        float4 v = *reinterpret_cast<const float4*>(
            st + (size_t)(m0 + row) * DIM_S + f4 * 4);
        uint32_t byte = OFF_A1 + row * 128
                      + (uint32_t)(((f4 >> 1) ^ (row & 7)) * 16 + 8 * (f4 & 1));
        *reinterpret_cast<uint2*>(smem + byte) =
            make_uint2(packh2(v.x, v.y), packh2(v.z, v.w));
    }
    __syncthreads();

    uint32_t accA[4][8][2], accB[4][8][2];
    #pragma unroll
    for (int a = 0; a < 4; a++)
        #pragma unroll
        for (int b = 0; b < 8; b++) {
            accA[a][b][0] = 0u; accA[a][b][1] = 0u;
        }

    // ---- layer 1 GEMM (K = 64, single f16 chain into accA) ----
    gemm<4, 8, 128>(pb1, sb + OFF_A1, accA, accB, lane);

    // ---- epilogue 1: H1 = hmax2(accA + b1h2, 0), direct half2 STS ----
    // phys col pair of accA[mt][nt][r2] = wn*64 + nt*8 + 2*(lane&3)
    {
        uint32_t b1p[8];
        #pragma unroll
        for (int nt = 0; nt < 8; nt++)
            b1p[nt] = smu[(OFF_B1 >> 2) + wn * 32 + nt * 4 + (lane & 3)];
        const int c0 = (lane >> 2) & 7;
        const uint32_t eb = OFF_H1 + (lane >> 2) * 512 + wn * 128
                          + 4 * (lane & 3);
        #pragma unroll
        for (int mt = 0; mt < 4; mt++) {
            const uint32_t ebm = eb + mt * 8192;
            #pragma unroll
            for (int nt = 0; nt < 8; nt++) {
                uint32_t p0 = hmax2z(hadd2u(accA[mt][nt][0], b1p[nt]));
                uint32_t p1 = hmax2z(hadd2u(accA[mt][nt][1], b1p[nt]));
                uint32_t by0 = ebm + (uint32_t)((nt ^ c0) * 16);
                *reinterpret_cast<uint32_t*>(smem + by0) = p0;
                *reinterpret_cast<uint32_t*>(smem + by0 + 4096) = p1;
            }
        }
    }
    #pragma unroll
    for (int a = 0; a < 4; a++)
        #pragma unroll
        for (int b = 0; b < 8; b++) {
            accA[a][b][0] = 0u; accA[a][b][1] = 0u;
            accB[a][b][0] = 0u; accB[a][b][1] = 0u;
        }

    __syncthreads();   // H1 visible

    // ---- layer 2 GEMM (K = 256): two 8-step f16 chains (accA, accB) ----
    gemm<16, 8, 512>(pb2, sb + OFF_H1, accA, accB, lane);

    // ---- epilogue 2: v = hmax2(accA+accB+b2) in half2; dot w3 in f32 ----
    {
        uint32_t b2p[8];
        float2 w3f[8];
        #pragma unroll
        for (int nt = 0; nt < 8; nt++) {
            int idx = wn * 32 + nt * 4 + (lane & 3);
            b2p[nt] = smu[(OFF_B2 >> 2) + idx];
            w3f[nt] = __half22float2(u2h(smu[(OFF_W3 >> 2) + idx]));
        }
        float p[4][2];
        #pragma unroll
        for (int mt = 0; mt < 4; mt++) { p[mt][0] = 0.f; p[mt][1] = 0.f; }
        #pragma unroll
        for (int mt = 0; mt < 4; mt++)
            #pragma unroll
            for (int nt = 0; nt < 8; nt++)
                #pragma unroll
                for (int r2 = 0; r2 < 2; r2++) {
                    uint32_t s = hadd2u(accA[mt][nt][r2], accB[mt][nt][r2]);
                    uint32_t v = hmax2z(hadd2u(s, b2p[nt]));
                    float2 fv = __half22float2(u2h(v));
                    p[mt][r2] += fv.x * w3f[nt].x + fv.y * w3f[nt].y;
                }
        #pragma unroll
        for (int off = 1; off <= 2; off <<= 1)
            #pragma unroll
            for (int mt = 0; mt < 4; mt++) {
                p[mt][0] += __shfl_xor_sync(0xFFFFFFFFu, p[mt][0], off);
                p[mt][1] += __shfl_xor_sync(0xFFFFFFFFu, p[mt][1], off);
            }
        if ((lane & 3) == 0) {
            #pragma unroll
            for (int mt = 0; mt < 4; mt++)
                #pragma unroll
                for (int h = 0; h < 2; h++) {
                    int row = mt * 16 + (lane >> 2) + 8 * h;
                    smf[(OFF_PART >> 2) + row * 4 + wn] = p[mt][h];
                }
        }
    }
    __syncthreads();
    if (tid < BM) {
        const float* q = smf + (OFF_PART >> 2) + tid * 4;
        out[(size_t)(m0 + tid) * NEXP + c] = q[0] + q[1] + q[2] + q[3] + b3[c];
    }
}

extern "C" void kernel_launch(void* const* d_in, const int* in_sizes, int n_in,
                              void* d_out, int out_size)
{
    const float* st = (const float*)d_in[0];
    const float* W1 = (const float*)d_in[1];
    const float* b1 = (const float*)d_in[2];
    const float* W2 = (const float*)d_in[3];
    const float* b2 = (const float*)d_in[4];
    const float* W3 = (const float*)d_in[5];
    const float* b3 = (const float*)d_in[6];
    float* out = (float*)d_out;

    const int total = NEXP * 4 * 4 * 512 + NEXP * 4 * 16 * 512;  // 327680
    convw<<<(total + 255) / 256, 256>>>(W1, W2);

    cudaFuncSetAttribute(moe_disc_mma,
                         cudaFuncAttributeMaxDynamicSharedMemorySize, SMEM_BYTES);
    dim3 grid(65536 / BM, NEXP);
    moe_disc_mma<<<grid, NTHR, SMEM_BYTES>>>(st, b1, b2, W3, b3, out);
}